// round 17
// baseline (speedup 1.0000x reference)
#include <cuda_runtime.h>
#include <cuda_fp16.h>
#include <cstdint>

#define B_N 2048
#define H_N 4096
#define E_N 8
#define L_N 512

// ---------------- scratch ----------------
__device__ int   g_counts[E_N];
__device__ int   g_rows[E_N][B_N];
__device__ float g_pen[25];
__device__ int   g_ntiles;
__device__ int   g_tile_ctr;
__device__ int   g_sel_done;
__device__ uint32_t g_tiles[512];

__device__ __align__(256) __half g_hid_h[B_N * H_N];
__device__ __align__(256) __half g_W_h[E_N * L_N * H_N];

// -------- fused converter: W -> fp16, hidden -> fp16, + init (block 0) -------
#define CVT_GRID 1184

__global__ void __launch_bounds__(256)
convert_kernel(const float* __restrict__ W, const float* __restrict__ hidden) {
    if (blockIdx.x == 0 && threadIdx.x < 32) {
        int t = threadIdx.x;
        if (t < E_N) g_counts[t] = 0;
        if (t < 25)  g_pen[t]    = 0.0f;
        if (t == 0) { g_tile_ctr = 0; g_sel_done = 0; }
    }
    const int WN4 = E_N * L_N * H_N / 4;   // 4194304
    const int HN4 = B_N * H_N / 4;         // 2097152
    const int stride = CVT_GRID * 256;
    int t0 = blockIdx.x * 256 + threadIdx.x;

    const float4* Wv = (const float4*)W;
    uint2* wh = (uint2*)g_W_h;
    for (int i = t0; i < WN4; i += stride) {
        float4 v = Wv[i];
        __half2 h01 = __floats2half2_rn(v.x, v.y);
        __half2 h23 = __floats2half2_rn(v.z, v.w);
        uint2 p;
        p.x = *reinterpret_cast<uint32_t*>(&h01);
        p.y = *reinterpret_cast<uint32_t*>(&h23);
        wh[i] = p;
    }
    const float4* hv = (const float4*)hidden;
    uint2* hh = (uint2*)g_hid_h;
    for (int i = t0; i < HN4; i += stride) {
        float4 v = hv[i];
        __half2 h01 = __floats2half2_rn(v.x, v.y);
        __half2 h23 = __floats2half2_rn(v.z, v.w);
        uint2 p;
        p.x = *reinterpret_cast<uint32_t*>(&h01);
        p.y = *reinterpret_cast<uint32_t*>(&h23);
        hh[i] = p;
    }
}

// -------- expert selection + split-K tile build (last-block ticket) ----------
// tile enc = e<<16 | mchunk<<8 | l<<2 | khalf
__global__ void select_kernel(const float* __restrict__ envs,
                              const int* __restrict__ idx32,
                              const float* __restrict__ gumbel) {
    int b = blockIdx.x * blockDim.x + threadIdx.x;
    if (b < B_N) {
        int stride = (idx32[1] == 0) ? 2 : 1;   // int64-on-disk detection (idx = arange)
        int r = idx32[(size_t)b * stride];
        if (r < 0) r = 0;
        if (r >= B_N) r = B_N - 1;
        const float* ev = envs   + (size_t)r * E_N;
        const float* gv = gumbel + (size_t)b * E_N;
        float best = ev[0] + gv[0];
        int be = 0;
#pragma unroll
        for (int e = 1; e < E_N; e++) {
            float v = ev[e] + gv[e];
            if (v > best) { best = v; be = e; }
        }
        int pos = atomicAdd(&g_counts[be], 1);
        g_rows[be][pos] = b;
    }
    __syncthreads();
    if (threadIdx.x == 0) {
        __threadfence();
        int tk = atomicAdd(&g_sel_done, 1);
        if (tk == (int)gridDim.x - 1) {
            int n = 0;
            for (int e = 0; e < E_N; e++) {
                int mc = (g_counts[e] + 63) >> 6;
                for (int m = 0; m < mc; m++)
                    for (int l = 0; l < 4; l++)
                        for (int kh = 0; kh < 2; kh++)
                            g_tiles[n++] = (e << 16) | (m << 8) | (l << 2) | kh;
            }
            g_ntiles = n;
        }
    }
}

// ------- penalty stats from fp16 W copy ----
#define ST_GRID 1024
#define ST_BLK  128

__global__ void __launch_bounds__(ST_BLK, 4)
stats_kernel() {
    const int LH4 = (L_N * H_N) / 4;
    const uint2* Wv = (const uint2*)g_W_h;
    const int stride = ST_GRID * ST_BLK;
    const int iters = LH4 / stride;    // 4

    float q[8], c[8], l1[8], ss = 0.0f;
#pragma unroll
    for (int e = 0; e < 8; e++) { q[e] = 0.f; c[e] = 0.f; l1[e] = 0.f; }

    int i = blockIdx.x * ST_BLK + threadIdx.x;

    uint2 buf[8];
#pragma unroll
    for (int e = 0; e < 8; e++) buf[e] = Wv[(size_t)e * LH4 + i];

    for (int it = 0; it < iters; it++) {
        uint2 nxt[8];
        int i2 = i + stride;
        if (it + 1 < iters) {
#pragma unroll
            for (int e = 0; e < 8; e++) nxt[e] = Wv[(size_t)e * LH4 + i2];
        }
        float w[8][4];
#pragma unroll
        for (int e = 0; e < 8; e++) {
            __half2 p0 = *reinterpret_cast<__half2*>(&buf[e].x);
            __half2 p1 = *reinterpret_cast<__half2*>(&buf[e].y);
            float2 f0 = __half22float2(p0);
            float2 f1 = __half22float2(p1);
            w[e][0] = f0.x; w[e][1] = f0.y; w[e][2] = f1.x; w[e][3] = f1.y;
        }
#pragma unroll
        for (int comp = 0; comp < 4; comp++) {
            float s = 0.f;
#pragma unroll
            for (int e = 0; e < 8; e++) s += w[e][comp];
            ss = fmaf(s, s, ss);
#pragma unroll
            for (int e = 0; e < 8; e++) {
                float we = w[e][comp];
                q[e]  = fmaf(we, we, q[e]);
                c[e]  = fmaf(we, s,  c[e]);
                l1[e] += fabsf(we);
            }
        }
        if (it + 1 < iters) {
#pragma unroll
            for (int e = 0; e < 8; e++) buf[e] = nxt[e];
            i = i2;
        }
    }

    __shared__ float red[25][136];
    int tid = threadIdx.x;
#pragma unroll
    for (int e = 0; e < 8; e++) {
        red[e][tid]      = q[e];
        red[8 + e][tid]  = c[e];
        red[16 + e][tid] = l1[e];
    }
    red[24][tid] = ss;
    __syncthreads();
    if (tid < 25) {
        float s = 0.f;
#pragma unroll 8
        for (int j = 0; j < ST_BLK; j++) s += red[tid][j];
        atomicAdd(&g_pen[tid], s);
    }
}

__global__ void finalize_kernel(float* __restrict__ pen_out) {
    if (threadIdx.x == 0) {
        float acc = 0.f;
        float ss = g_pen[24];
#pragma unroll
        for (int e = 0; e < 8; e++) {
            float diff = g_pen[e] - 0.25f * g_pen[8 + e] + ss * (1.0f / 64.0f);
            float l1 = g_pen[16 + e];
            acc += diff / (l1 * l1);
        }
        pen_out[0] = acc * 0.125f;
    }
}

// ====== persistent fp16 GEMM, split-K x2, 2 CTA/SM ======
// CTA tile 64(M) x 128(N) x 2048(K-half); 256 threads = 8 warps (2M x 4N), 32x32.
// Stage = 48KB (TK=128 as 2x64 k-blocks); NSTAGE=2 -> 97KB/CTA -> 2 CTA/SM.
// Epilogue: atomicAdd (exactly 2 contributions per element; out pre-zeroed).

#define TMB 64
#define TNB 128
#define TK 128
#define KSPLIT 2048
#define NSTAGE 2
#define STG_B 49152
#define NIT (KSPLIT / TK)       // 16
#define SMEM_DYN (NSTAGE * STG_B + 1024)
#define GRID_GEMM 296

static __device__ __forceinline__ uint32_t s2u(const void* p) {
    return (uint32_t)__cvta_generic_to_shared(p);
}
static __device__ __forceinline__ void cp16(uint32_t s, const __half* g, bool pred) {
    int sz = pred ? 16 : 0;
    asm volatile("cp.async.cg.shared.global [%0], [%1], 16, %2;"
                 :: "r"(s), "l"(g), "r"(sz));
}

#define LDSM4(r0, r1, r2, r3, a) \
    asm volatile("ldmatrix.sync.aligned.m8n8.x4.shared.b16 {%0,%1,%2,%3}, [%4];" \
                 : "=r"(r0), "=r"(r1), "=r"(r2), "=r"(r3) : "r"(a))

#define MMAF16(d, A, b0, b1) \
    asm volatile("mma.sync.aligned.m16n8k16.row.col.f32.f16.f16.f32 " \
                 "{%0,%1,%2,%3}, {%4,%5,%6,%7}, {%8,%9}, {%0,%1,%2,%3};" \
                 : "+f"((d)[0]), "+f"((d)[1]), "+f"((d)[2]), "+f"((d)[3]) \
                 : "r"((A)[0]), "r"((A)[1]), "r"((A)[2]), "r"((A)[3]), \
                   "r"(b0), "r"(b1))

extern __shared__ char dyn_raw[];

__global__ void __launch_bounds__(256, 2)
gemm_kernel(float* __restrict__ out) {
    __shared__ int rowids[TMB];
    __shared__ int s_tile;

    int tid = threadIdx.x;
    int wid = tid >> 5, lane = tid & 31;

    uint32_t sbase = (s2u(dyn_raw) + 1023) & ~1023u;
    uint32_t stb[NSTAGE];
#pragma unroll
    for (int s = 0; s < NSTAGE; s++) stb[s] = sbase + s * STG_B;

    int lrow = tid >> 3;              // 0..31
    int lcc  = tid & 7;
    int lphys = lcc ^ (lrow & 7);
    int sOffA[2], sOffB[4];
#pragma unroll
    for (int i = 0; i < 2; i++) sOffA[i] = ((lrow + i * 32) * 64 + lphys * 8) * 2;
#pragma unroll
    for (int i = 0; i < 4; i++) sOffB[i] = ((lrow + i * 32) * 64 + lphys * 8) * 2;

    int wm = (wid & 1) * 32;
    int wn = (wid >> 1) * 32;
    int a_h = lane >> 4, a_r = lane & 15;
    int b_g = lane >> 3, b_sub = b_g >> 1, b_h = b_g & 1, b_r = lane & 7;

    int arow[2], axr[2];
#pragma unroll
    for (int mt = 0; mt < 2; mt++) {
        int r = wm + mt * 16 + a_r;
        arow[mt] = r * 64; axr[mt] = r & 7;
    }
    int brow[2], bxr[2];
#pragma unroll
    for (int p = 0; p < 2; p++) {
        int r = wn + p * 16 + b_sub * 8 + b_r;
        brow[p] = r * 64; bxr[p] = r & 7;
    }
    int gid = lane >> 2, tig = lane & 3;

    for (;;) {
        __syncthreads();   // previous tile fully done
        if (tid == 0) s_tile = atomicAdd(&g_tile_ctr, 1);
        __syncthreads();
        int t = s_tile;
        if (t >= g_ntiles) break;

        uint32_t enc = g_tiles[t];
        int e = enc >> 16;
        int mch = (enc >> 8) & 255;
        int l_base = ((enc >> 2) & 3) * TNB;
        int kh = (enc & 1) * KSPLIT;
        int cnt = g_counts[e];

        if (tid < TMB) {
            int i = mch * TMB + tid;
            rowids[tid] = (i < cnt) ? g_rows[e][i] : -1;
        }
        __syncthreads();

        const __half* gA[2];
        const __half* gB[4];
        bool apred[2];
#pragma unroll
        for (int i = 0; i < 2; i++) {
            int row = lrow + i * 32;
            int g = rowids[row];
            apred[i] = (g >= 0);
            gA[i] = g_hid_h + (size_t)(apred[i] ? g : 0) * H_N + kh + lcc * 8;
        }
#pragma unroll
        for (int i = 0; i < 4; i++) {
            int row = lrow + i * 32;
            gB[i] = g_W_h + ((size_t)e * L_N + l_base + row) * H_N + kh + lcc * 8;
        }

        float acc[2][4][4];
#pragma unroll
        for (int mt = 0; mt < 2; mt++)
#pragma unroll
            for (int nt = 0; nt < 4; nt++)
#pragma unroll
                for (int j = 0; j < 4; j++) acc[mt][nt][j] = 0.f;

        // preload stage 0
        {
            uint32_t b = stb[0];
#pragma unroll
            for (int kb = 0; kb < 2; kb++) {
                int ko = kb * 64;
#pragma unroll
                for (int i = 0; i < 2; i++)
                    cp16(b + kb * 8192 + sOffA[i], gA[i] + ko, apred[i]);
#pragma unroll
                for (int i = 0; i < 4; i++)
                    cp16(b + 16384 + kb * 16384 + sOffB[i], gB[i] + ko, true);
            }
            asm volatile("cp.async.commit_group;");
        }

        for (int it = 0; it < NIT; it++) {
            asm volatile("cp.async.wait_group 0;");
            __syncthreads();

            if (it + 1 < NIT) {
                uint32_t b = stb[(it + 1) & 1];
                int koff = (it + 1) * TK;
#pragma unroll
                for (int kb = 0; kb < 2; kb++) {
                    int ko = koff + kb * 64;
#pragma unroll
                    for (int i = 0; i < 2; i++)
                        cp16(b + kb * 8192 + sOffA[i], gA[i] + ko, apred[i]);
#pragma unroll
                    for (int i = 0; i < 4; i++)
                        cp16(b + 16384 + kb * 16384 + sOffB[i], gB[i] + ko, true);
                }
                asm volatile("cp.async.commit_group;");
            }

            uint32_t base = stb[it & 1];
#pragma unroll
            for (int s4 = 0; s4 < 8; s4++) {
                uint32_t AS = base + (s4 >> 2) * 8192;
                uint32_t BS = base + 16384 + (s4 >> 2) * 16384;
                int s4l = s4 & 3;
                uint32_t af[2][4], bf[4][2];
#pragma unroll
                for (int mt = 0; mt < 2; mt++) {
                    int ch = (2 * s4l + a_h) ^ axr[mt];
                    LDSM4(af[mt][0], af[mt][1], af[mt][2], af[mt][3],
                          AS + (arow[mt] + ch * 8) * 2);
                }
#pragma unroll
                for (int p = 0; p < 2; p++) {
                    int ch = (2 * s4l + b_h) ^ bxr[p];
                    uint32_t r0, r1, r2, r3;
                    LDSM4(r0, r1, r2, r3, BS + (brow[p] + ch * 8) * 2);
                    bf[2 * p][0] = r0; bf[2 * p][1] = r1;
                    bf[2 * p + 1][0] = r2; bf[2 * p + 1][1] = r3;
                }
#pragma unroll
                for (int mt = 0; mt < 2; mt++)
#pragma unroll
                    for (int nt = 0; nt < 4; nt++)
                        MMAF16(acc[mt][nt], af[mt], bf[nt][0], bf[nt][1]);
            }
        }

        // ---- epilogue: atomic accumulate (2 contributions/element) ----
#pragma unroll
        for (int mt = 0; mt < 2; mt++) {
            int r0 = wm + mt * 16 + gid;
            int r1 = r0 + 8;
            int g0 = rowids[r0];
            int g1 = rowids[r1];
#pragma unroll
            for (int nt = 0; nt < 4; nt++) {
                int col = l_base + wn + nt * 8 + tig * 2;
                if (g0 >= 0) {
                    float* p = out + (size_t)g0 * L_N + col;
                    atomicAdd(p,     acc[mt][nt][0]);
                    atomicAdd(p + 1, acc[mt][nt][1]);
                }
                if (g1 >= 0) {
                    float* p = out + (size_t)g1 * L_N + col;
                    atomicAdd(p,     acc[mt][nt][2]);
                    atomicAdd(p + 1, acc[mt][nt][3]);
                }
            }
        }
    }
}

// ---------------- launch ----------------
extern "C" void kernel_launch(void* const* d_in, const int* in_sizes, int n_in,
                              void* d_out, int out_size) {
    const float* hidden = (const float*)d_in[0];
    const float* envs   = (const float*)d_in[1];
    const int*   idx32  = (const int*)d_in[2];
    const float* gumbel = (const float*)d_in[3];
    const float* W      = (const float*)d_in[4];
    float* out = (float*)d_out;

    cudaFuncSetAttribute(gemm_kernel,
                         cudaFuncAttributeMaxDynamicSharedMemorySize, SMEM_DYN);

    convert_kernel<<<CVT_GRID, 256>>>(W, hidden);            // + init (block 0)
    select_kernel<<<B_N / 256, 256>>>(envs, idx32, gumbel);  // + tile build
    stats_kernel<<<ST_GRID, ST_BLK>>>();                     // penalty stats
    cudaMemsetAsync(out, 0, (size_t)B_N * L_N * sizeof(float));

    gemm_kernel<<<GRID_GEMM, 256, SMEM_DYN>>>(out);

    if (out_size > B_N * L_N)
        finalize_kernel<<<1, 32>>>(out + (size_t)B_N * L_N);
}